// round 1
// baseline (speedup 1.0000x reference)
#include <cuda_runtime.h>
#include <cstdint>

#define NPTS   34100
#define BATCHN 8
#define NGT    200
#define NLVL   5
#define NCAND  3500
#define MAXDET 300
#define IMGF   1280.0f
#define BIGF   2147483648.0f   // float32(2^31 - 1)

// output layout (float32, tuple flattened in return order)
#define OFF_MATCH  0
#define OFF_BOXES  272800
#define OFF_SCORES 282400
#define OFF_LABELS 284800
#define OFF_VALID  287200

__constant__ int c_loff[NLVL]  = {0, 25600, 32000, 33600, 34000};
__constant__ int c_lsize[NLVL] = {25600, 6400, 1600, 400, 100};
__constant__ int c_k[NLVL]     = {1000, 1000, 1000, 400, 100};
__constant__ int c_cbase[NLVL] = {0, 1000, 2000, 3000, 3400};

// scratch (static device globals; no allocation)
__device__ unsigned long long g_keys[BATCHN * NPTS];
__device__ float  g_cscore[BATCHN * NCAND];
__device__ float4 g_cbox[BATCHN * NCAND];
__device__ int    g_cgidx[BATCHN * NCAND];

// ---------------------------------------------------------------------------
// Stage 1: point -> gt box matching (argmin of area among containing boxes)
// ---------------------------------------------------------------------------
__global__ void match_kernel(const float* __restrict__ points,
                             const float* __restrict__ gt,
                             float* __restrict__ out) {
    const int b = blockIdx.y;
    __shared__ float sx1[NGT], sy1[NGT], sx2[NGT], sy2[NGT], sar[NGT];
    for (int j = threadIdx.x; j < NGT; j += blockDim.x) {
        const float* g = gt + (size_t)(b * NGT + j) * 4;
        float x1 = g[0], y1 = g[1], x2 = g[2], y2 = g[3];
        sx1[j] = x1; sy1[j] = y1; sx2[j] = x2; sy2[j] = y2;
        sar[j] = (x2 - x1) * (y2 - y1);
    }
    __syncthreads();
    int p = blockIdx.x * blockDim.x + threadIdx.x;
    if (p >= NPTS) return;
    float px = points[2 * p], py = points[2 * p + 1];
    float best = 3.4e38f;
    int bi = 0;
    bool any = false;
    #pragma unroll 4
    for (int j = 0; j < NGT; ++j) {
        bool in = (px >= sx1[j]) && (px <= sx2[j]) && (py >= sy1[j]) && (py <= sy2[j]);
        any = any || in;
        float c = in ? sar[j] : BIGF;
        if (c < best) { best = c; bi = j; }   // strict <  == first-min (jnp.argmin)
    }
    out[OFF_MATCH + (size_t)b * NPTS + p] = (float)(any ? bi : -1);
}

// ---------------------------------------------------------------------------
// Stage 2: exact per-(batch,level) top-k via 64-bit radix select on unique
// keys (ordered_score<<32 | ~local_idx), then compaction + box decode/clip.
// ---------------------------------------------------------------------------
__global__ void topk_kernel(const float* __restrict__ cls,
                            const float* __restrict__ reg,
                            const float* __restrict__ points) {
    const int bl = blockIdx.x;
    const int b = bl / NLVL, lvl = bl % NLVL;
    const int loff = c_loff[lvl], n = c_lsize[lvl], k = c_k[lvl];
    unsigned long long* keys = g_keys + (size_t)b * NPTS + loff;
    const float* logit = cls + (size_t)b * NPTS + loff;

    // phase 1: build keys
    for (int i = threadIdx.x; i < n; i += blockDim.x) {
        float s = 1.0f / (1.0f + expf(-logit[i]));   // sigmoid
        unsigned int u = __float_as_uint(s);
        u = (u & 0x80000000u) ? ~u : (u | 0x80000000u);  // order-preserving
        keys[i] = ((unsigned long long)u << 32) |
                  (unsigned long long)(0xFFFFFFFFu - (unsigned)i);
    }
    __syncthreads();

    // phase 2: radix select the exact k-th largest key (keys are unique)
    __shared__ unsigned int hist[256];
    __shared__ unsigned long long s_pref;
    __shared__ int s_remk;
    unsigned long long prefix = 0ULL;
    int remk = k;
    for (int pass = 0; pass < 8; ++pass) {
        const int shift = 56 - 8 * pass;
        const unsigned long long pmask =
            pass ? (~0ULL << (unsigned)(shift + 8)) : 0ULL;
        if (threadIdx.x < 256) hist[threadIdx.x] = 0u;
        __syncthreads();
        for (int i = threadIdx.x; i < n; i += blockDim.x) {
            unsigned long long kk = keys[i];
            if ((kk & pmask) == prefix)
                atomicAdd(&hist[(unsigned)(kk >> shift) & 0xFFu], 1u);
        }
        __syncthreads();
        if (threadIdx.x == 0) {
            int r = remk;
            int bin = 255;
            for (; bin > 0; --bin) {
                int h = (int)hist[bin];
                if (r <= h) break;
                r -= h;
            }
            s_pref = prefix | ((unsigned long long)bin << shift);
            s_remk = r;
        }
        __syncthreads();
        prefix = s_pref;
        remk = s_remk;
        __syncthreads();
    }
    // threshold = prefix; exactly k keys satisfy key >= prefix

    // phase 3: compaction (order irrelevant; NMS tie-breaks on global index)
    __shared__ int s_cnt;
    if (threadIdx.x == 0) s_cnt = 0;
    __syncthreads();
    const int cbase = b * NCAND + c_cbase[lvl];
    for (int i = threadIdx.x; i < n; i += blockDim.x) {
        unsigned long long kk = keys[i];
        if (kk >= prefix) {
            int slot = atomicAdd(&s_cnt, 1);
            int gidx = loff + i;
            unsigned int u = (unsigned int)(kk >> 32);
            unsigned int fb = (u & 0x80000000u) ? (u ^ 0x80000000u) : ~u;
            float score = __uint_as_float(fb);
            const float* rg = reg + ((size_t)b * NPTS + gidx) * 4;
            float px = points[2 * gidx], py = points[2 * gidx + 1];
            float l = rg[0] * IMGF, t = rg[1] * IMGF;
            float r = rg[2] * IMGF, bt = rg[3] * IMGF;
            float x1 = fminf(fmaxf(px - l, 0.0f), IMGF);
            float y1 = fminf(fmaxf(py - t, 0.0f), IMGF);
            float x2 = fminf(fmaxf(px + r, 0.0f), IMGF);
            float y2 = fminf(fmaxf(py + bt, 0.0f), IMGF);
            int ci = cbase + slot;
            g_cscore[ci] = score;
            g_cbox[ci] = make_float4(x1, y1, x2, y2);
            g_cgidx[ci] = gidx;
        }
    }
}

// ---------------------------------------------------------------------------
// Stage 3: sequential NMS, one block per batch image. Candidates are
// register-resident; argmax key = (ordered_score<<32 | ~global_idx) so ties
// resolve to lowest global index, matching the reference's candidate order.
// ---------------------------------------------------------------------------
__global__ void __launch_bounds__(1024, 1)
nms_kernel(float* __restrict__ out) {
    const int b = blockIdx.x;
    const int tid = threadIdx.x;
    const int lane = tid & 31, wid = tid >> 5;

    float cx1[4], cy1[4], cx2[4], cy2[4], car[4], csc[4];
    unsigned long long ckey[4];
    #pragma unroll
    for (int c = 0; c < 4; ++c) {
        int idx = tid + c * 1024;
        if (idx < NCAND) {
            int ci = b * NCAND + idx;
            float4 bx = g_cbox[ci];
            float sc = g_cscore[ci];
            int gi = g_cgidx[ci];
            cx1[c] = bx.x; cy1[c] = bx.y; cx2[c] = bx.z; cy2[c] = bx.w;
            car[c] = (bx.z - bx.x) * (bx.w - bx.y);
            csc[c] = sc;
            unsigned int u = __float_as_uint(sc);
            u = (u & 0x80000000u) ? ~u : (u | 0x80000000u);
            ckey[c] = (sc > 0.05f)
                    ? (((unsigned long long)u << 32) |
                       (unsigned long long)(~(unsigned)gi))
                    : 0ULL;
        } else {
            ckey[c] = 0ULL;
            cx1[c] = cy1[c] = cx2[c] = cy2[c] = car[c] = csc[c] = 0.0f;
        }
    }

    __shared__ unsigned long long s_warp[32];
    __shared__ unsigned long long s_max;
    __shared__ float s_pick[5];

    for (int it = 0; it < MAXDET; ++it) {
        // block argmax over 64-bit keys
        unsigned long long v = 0ULL;
        #pragma unroll
        for (int c = 0; c < 4; ++c) if (ckey[c] > v) v = ckey[c];
        #pragma unroll
        for (int o = 16; o; o >>= 1) {
            unsigned long long w = __shfl_down_sync(0xFFFFFFFFu, v, o);
            if (w > v) v = w;
        }
        if (lane == 0) s_warp[wid] = v;
        __syncthreads();
        if (wid == 0) {
            v = s_warp[lane];
            #pragma unroll
            for (int o = 16; o; o >>= 1) {
                unsigned long long w = __shfl_down_sync(0xFFFFFFFFu, v, o);
                if (w > v) v = w;
            }
            if (lane == 0) s_max = v;
        }
        __syncthreads();
        unsigned long long mk = s_max;
        const int oslot = b * MAXDET + it;

        if (mk == 0ULL) {
            if (tid == 0) {
                out[OFF_BOXES + (size_t)oslot * 4 + 0] = 0.0f;
                out[OFF_BOXES + (size_t)oslot * 4 + 1] = 0.0f;
                out[OFF_BOXES + (size_t)oslot * 4 + 2] = 0.0f;
                out[OFF_BOXES + (size_t)oslot * 4 + 3] = 0.0f;
                out[OFF_SCORES + oslot] = 0.0f;
                out[OFF_LABELS + oslot] = -1.0f;
                out[OFF_VALID + oslot] = 0.0f;
            }
            continue;  // uniform branch; all subsequent iterations also dead
        }

        // owner writes output + broadcast picked box
        #pragma unroll
        for (int c = 0; c < 4; ++c) {
            if (ckey[c] == mk) {
                out[OFF_BOXES + (size_t)oslot * 4 + 0] = cx1[c];
                out[OFF_BOXES + (size_t)oslot * 4 + 1] = cy1[c];
                out[OFF_BOXES + (size_t)oslot * 4 + 2] = cx2[c];
                out[OFF_BOXES + (size_t)oslot * 4 + 3] = cy2[c];
                out[OFF_SCORES + oslot] = csc[c];
                out[OFF_LABELS + oslot] = 0.0f;
                out[OFF_VALID + oslot] = 1.0f;
                s_pick[0] = cx1[c]; s_pick[1] = cy1[c];
                s_pick[2] = cx2[c]; s_pick[3] = cy2[c];
                s_pick[4] = car[c];
                ckey[c] = 0ULL;
            }
        }
        __syncthreads();
        float p1 = s_pick[0], p2 = s_pick[1], p3 = s_pick[2], p4 = s_pick[3];
        float pa = s_pick[4];
        #pragma unroll
        for (int c = 0; c < 4; ++c) {
            if (ckey[c] != 0ULL) {
                float xx1 = fmaxf(p1, cx1[c]);
                float yy1 = fmaxf(p2, cy1[c]);
                float xx2 = fminf(p3, cx2[c]);
                float yy2 = fminf(p4, cy2[c]);
                float inter = fmaxf(xx2 - xx1, 0.0f) * fmaxf(yy2 - yy1, 0.0f);
                float iou = inter / (pa + car[c] - inter + 1e-9f);
                if (iou > 0.5f) ckey[c] = 0ULL;
            }
        }
        // no sync needed: next iteration's reduce syncs order s_pick reuse
    }
}

extern "C" void kernel_launch(void* const* d_in, const int* in_sizes, int n_in,
                              void* d_out, int out_size) {
    const float* points = (const float*)d_in[0];   // (34100, 2)
    const float* gt     = (const float*)d_in[1];   // (8, 200, 4)
    const float* cls    = (const float*)d_in[2];   // (8, 34100, 1)
    const float* reg    = (const float*)d_in[3];   // (8, 34100, 4)
    float* out = (float*)d_out;

    dim3 mg((NPTS + 255) / 256, BATCHN);
    match_kernel<<<mg, 256>>>(points, gt, out);
    topk_kernel<<<BATCHN * NLVL, 1024>>>(cls, reg, points);
    nms_kernel<<<BATCHN, 1024>>>(out);
}